// round 13
// baseline (speedup 1.0000x reference)
#include <cuda_runtime.h>
#include <cuda_fp16.h>
#include <cstdint>

#define H_DIM 1024
#define S_DIM 2048
#define B_DIM 32
#define M_TILE 64
#define N_PASS 256
#define KC 64
#define NUM_G 64            // 4 passes x 16 K-chunks

// smem layout: score | A-resident (16 blocks x 64 rows x 128B) | 3 B stages
#define SMEM_SCORE 0
#define SMEM_A     1024
#define A_BYTES    131072           // 64 x 1024 fp16
#define SMEM_BST   (SMEM_A + A_BYTES)
#define BSTAGE_SZ  32768            // 256 rows x 128B
#define SMEM_TOTAL (SMEM_BST + 3 * BSTAGE_SZ)   // 230400 <= 232448 opt-in

__device__ __align__(16) __half g_ut[(size_t)H_DIM * H_DIM];   // Ua^T fp16, 2MB (L2-resident)
__device__ float g_dvec[B_DIM * H_DIM];

__device__ __forceinline__ uint32_t smem_u32(const void* p) {
    uint32_t a;
    asm("{ .reg .u64 t; cvta.to.shared.u64 t, %1; cvt.u32.u64 %0, t; }" : "=r"(a) : "l"(p));
    return a;
}
__device__ __forceinline__ void cp16(uint32_t s, const void* g) {
    asm volatile("cp.async.cg.shared.global [%0], [%1], 16;" :: "r"(s), "l"(g));
}
#define CP_COMMIT() asm volatile("cp.async.commit_group;" ::: "memory")
#define CP_WAIT1()  asm volatile("cp.async.wait_group 1;" ::: "memory")
#define STS128(a, r0, r1, r2, r3) \
    asm volatile("st.shared.v4.b32 [%0], {%1,%2,%3,%4};" \
                 :: "r"(a), "r"(r0), "r"(r1), "r"(r2), "r"(r3))

__device__ __forceinline__ void ldm4(uint32_t& r0, uint32_t& r1, uint32_t& r2, uint32_t& r3,
                                     uint32_t a) {
    asm volatile("ldmatrix.sync.aligned.m8n8.x4.shared.b16 {%0,%1,%2,%3}, [%4];"
                 : "=r"(r0), "=r"(r1), "=r"(r2), "=r"(r3) : "r"(a));
}
__device__ __forceinline__ void mma16816(float* c, const uint32_t* a, uint32_t b0, uint32_t b1) {
    asm volatile("mma.sync.aligned.m16n8k16.row.col.f32.f16.f16.f32 "
                 "{%0,%1,%2,%3}, {%4,%5,%6,%7}, {%8,%9}, {%0,%1,%2,%3};"
                 : "+f"(c[0]), "+f"(c[1]), "+f"(c[2]), "+f"(c[3])
                 : "r"(a[0]), "r"(a[1]), "r"(a[2]), "r"(a[3]), "r"(b0), "r"(b1));
}

// FMA/ALU-only tanh (no MUFU): exp2 range reduction + deg-5 poly + Newton rcp. abs err ~3e-5.
__device__ __forceinline__ float fast_tanh(float x) {
    x = fminf(9.0f, fmaxf(-9.0f, x));
    const float C = 2.885390082f;
    float zm = fmaf(x, C, 12582912.0f);
    int nb = __float_as_int(zm);
    float nf = zm - 12582912.0f;
    float f = fmaf(x, C, -nf);
    float p = 1.3333558e-3f;
    p = fmaf(p, f, 9.6181291e-3f);
    p = fmaf(p, f, 5.5504109e-2f);
    p = fmaf(p, f, 2.4022651e-1f);
    p = fmaf(p, f, 6.9314718e-1f);
    p = fmaf(p, f, 1.0f);
    float E = p * __int_as_float((nb + (127 - 0x4B400000)) << 23);
    float D = E + 1.0f;
    float r = __int_as_float((int)(0x7EF127EAu - (uint32_t)__float_as_int(D)));
    r = r * fmaf(-D, r, 2.0f);
    r = r * fmaf(-D, r, 2.0f);
    r = r * fmaf(-D, r, 2.0f);
    return fmaf(-2.0f, r, 1.0f);
}

// ---------------- Ut[k][h] = Ua[h][k] as fp16 ----------------
__global__ void ut_split_kernel(const float* __restrict__ ua_w) {
    __shared__ float tile[32][33];
    int tx = threadIdx.x, ty = threadIdx.y;
    int k = blockIdx.x * 32 + tx, h0 = blockIdx.y * 32;
    #pragma unroll
    for (int i = 0; i < 32; i += 8)
        tile[ty + i][tx] = ua_w[(size_t)(h0 + ty + i) * H_DIM + k];
    __syncthreads();
    #pragma unroll
    for (int i = 0; i < 32; i += 8) {
        int kk = blockIdx.x * 32 + ty + i;
        g_ut[(size_t)kk * H_DIM + h0 + tx] = __float2half(tile[tx][ty + i]);
    }
}

// ---------------- dvec[b,k] = Wa_b[k]+Ua_b[k] + sum_h dec[b,h]*Wa[h,k] ----------------
__global__ void __launch_bounds__(256) dvec_kernel(
    const float* __restrict__ dec, const float* __restrict__ wa_w,
    const float* __restrict__ wa_b, const float* __restrict__ ua_b) {
    __shared__ float ds[H_DIM];
    int b = blockIdx.x >> 2, kc = blockIdx.x & 3, tid = threadIdx.x;
    #pragma unroll
    for (int i = 0; i < 4; ++i) ds[tid + i * 256] = dec[b * H_DIM + tid + i * 256];
    __syncthreads();
    int k = kc * 256 + tid;
    float acc = wa_b[k] + ua_b[k];
    #pragma unroll 8
    for (int h = 0; h < H_DIM; ++h) acc += ds[h] * __ldg(&wa_w[(size_t)h * H_DIM + k]);
    g_dvec[b * H_DIM + k] = acc;
}

// ---------------- fused GEMM + tanh + Va-dot -> raw scores ----------------
// A (64 x 1024) resident in SMEM as fp16 (converted once); mainloop streams only B.
__global__ void __launch_bounds__(256, 1) gemm_kernel(
    const float* __restrict__ enc, const float* __restrict__ va_w,
    float* __restrict__ scores) {
    extern __shared__ __align__(1024) char smem[];
    uint32_t sb = smem_u32(smem);
    int tid = threadIdx.x, lane = tid & 31, wid = tid >> 5;
    int warp_m = wid >> 2, warp_n = wid & 3;     // 2 x 4 warps: M=32, N=64 each
    int m0 = blockIdx.x * M_TILE;
    int bidx = m0 >> 11;
    const float* dv = g_dvec + bidx * H_DIM;

    float* s_score = (float*)(smem + SMEM_SCORE);
    if (tid < M_TILE) s_score[tid] = 0.f;

    // ---- A prologue: load enc fp32, convert to fp16, store swizzled (once) ----
    {
        int row = tid >> 3, ch = tid & 7;            // item 0: rows 0..31
        int row2 = row + 32;                          // item 1: rows 32..63
        uint32_t d0 = sb + SMEM_A + row * 128 + ((ch ^ (row & 7)) << 4);
        uint32_t d1 = sb + SMEM_A + row2 * 128 + ((ch ^ (row2 & 7)) << 4);
        const float* s0 = enc + (size_t)(m0 + row) * H_DIM + ch * 8;
        const float* s1 = enc + (size_t)(m0 + row2) * H_DIM + ch * 8;
        #pragma unroll 4
        for (int blk = 0; blk < 16; ++blk) {
            float4 v0 = ((const float4*)(s0 + blk * 64))[0];
            float4 v1 = ((const float4*)(s0 + blk * 64))[1];
            float4 w0 = ((const float4*)(s1 + blk * 64))[0];
            float4 w1 = ((const float4*)(s1 + blk * 64))[1];
            __half2 a0 = __floats2half2_rn(v0.x, v0.y), a1 = __floats2half2_rn(v0.z, v0.w);
            __half2 a2 = __floats2half2_rn(v1.x, v1.y), a3 = __floats2half2_rn(v1.z, v1.w);
            __half2 b0 = __floats2half2_rn(w0.x, w0.y), b1 = __floats2half2_rn(w0.z, w0.w);
            __half2 b2 = __floats2half2_rn(w1.x, w1.y), b3 = __floats2half2_rn(w1.z, w1.w);
            STS128(d0 + blk * 8192, *(uint32_t*)&a0, *(uint32_t*)&a1, *(uint32_t*)&a2, *(uint32_t*)&a3);
            STS128(d1 + blk * 8192, *(uint32_t*)&b0, *(uint32_t*)&b1, *(uint32_t*)&b2, *(uint32_t*)&b3);
        }
    }

    // hoisted ldmatrix addressing
    int r8 = lane & 7, sel = lane >> 3;
    int selb = (sel & 1) << 3, selc = sel >> 1;
    uint32_t aRow = (uint32_t)((warp_m * 32 + selb + r8) * 128);
    uint32_t bOff = (uint32_t)((warp_n * 64 + selb + r8) * 128);
    uint32_t csw[4];
    #pragma unroll
    for (int ks = 0; ks < 4; ++ks) csw[ks] = (uint32_t)(((ks * 2 + selc) ^ r8) << 4);

    // hoisted B-fill addressing: 256 rows x 8 chunks / 256 threads = 8 items
    int brow[8], bswf[8], bch[8];
    #pragma unroll
    for (int i = 0; i < 8; ++i) {
        int idx = tid + i * 256;
        brow[i] = idx >> 3; bch[i] = idx & 7;
        bswf[i] = brow[i] * 128 + ((bch[i] ^ (brow[i] & 7)) << 4);
    }

    uint32_t stg[3];
    stg[0] = sb + SMEM_BST; stg[1] = stg[0] + BSTAGE_SZ; stg[2] = stg[1] + BSTAGE_SZ;

    float acc[2][8][4] = {};
    float partial[4] = {};

    // ---- B prologue: stages 0,1 (chunks 0,1 of pass 0) ----
    #pragma unroll
    for (int g = 0; g < 2; ++g) {
        int k0 = g * KC;
        #pragma unroll
        for (int i = 0; i < 8; ++i)
            cp16(stg[g] + bswf[i], g_ut + (size_t)brow[i] * H_DIM + k0 + bch[i] * 8);
        CP_COMMIT();
    }

    // ---- main: 64 chunks, one barrier per chunk, 3-stage B pipeline ----
    for (int g = 0; g < NUM_G; ++g) {
        CP_WAIT1();
        __syncthreads();          // also orders A-prologue STS on first iteration

        int gf = g + 2;
        if (gf < NUM_G) {
            int k0f = (gf & 15) * KC;
            int n0f = (gf >> 4) * N_PASS;
            uint32_t stf = stg[gf % 3];
            #pragma unroll
            for (int i = 0; i < 8; ++i)
                cp16(stf + bswf[i], g_ut + (size_t)(n0f + brow[i]) * H_DIM + k0f + bch[i] * 8);
        }
        CP_COMMIT();

        uint32_t sA = sb + SMEM_A + (g & 15) * 8192 + aRow;
        uint32_t sB = stg[g % 3] + bOff;
        #pragma unroll
        for (int ks = 0; ks < 4; ++ks) {
            uint32_t aAdr = sA + csw[ks], bAdr = sB + csw[ks];
            uint32_t a[2][4], b[4][4];
            #pragma unroll
            for (int mf = 0; mf < 2; ++mf)
                ldm4(a[mf][0], a[mf][1], a[mf][2], a[mf][3], aAdr + mf * 2048);
            #pragma unroll
            for (int nf2 = 0; nf2 < 4; ++nf2)
                ldm4(b[nf2][0], b[nf2][1], b[nf2][2], b[nf2][3], bAdr + nf2 * 2048);
            #pragma unroll
            for (int mf = 0; mf < 2; ++mf)
                #pragma unroll
                for (int nf = 0; nf < 8; ++nf)
                    mma16816(acc[mf][nf], a[mf], b[nf >> 1][nf & 1], b[nf >> 1][(nf & 1) + 2]);
        }

        // per-pass epilogue: tanh(acc + dvec) . Va  (dvec/Va from L2-hot global)
        if ((g & 15) == 15) {
            int n0 = (g >> 4) * N_PASS;
            #pragma unroll
            for (int nf = 0; nf < 8; ++nf) {
                int col = n0 + warp_n * 64 + nf * 8 + (lane & 3) * 2;
                float2 d = __ldg((const float2*)(dv + col));
                float2 vv = __ldg((const float2*)(va_w + col));
                #pragma unroll
                for (int mf = 0; mf < 2; ++mf) {
                    float* c = acc[mf][nf];
                    partial[mf * 2 + 0] += vv.x * fast_tanh(c[0] + d.x) +
                                           vv.y * fast_tanh(c[1] + d.y);
                    partial[mf * 2 + 1] += vv.x * fast_tanh(c[2] + d.x) +
                                           vv.y * fast_tanh(c[3] + d.y);
                    c[0] = c[1] = c[2] = c[3] = 0.f;
                }
            }
        }
    }

    // reduce per-thread partials -> per-row scores
    #pragma unroll
    for (int p = 0; p < 4; ++p) {
        float v = partial[p];
        v += __shfl_xor_sync(0xFFFFFFFFu, v, 1);
        v += __shfl_xor_sync(0xFFFFFFFFu, v, 2);
        if ((lane & 3) == 0) {
            int row = warp_m * 32 + (p >> 1) * 16 + (p & 1) * 8 + (lane >> 2);
            atomicAdd(&s_score[row], v);
        }
    }
    __syncthreads();
    if (tid < M_TILE) scores[m0 + tid] = s_score[tid];
}

// ---------------- masked softmax over S, in place ----------------
__global__ void __launch_bounds__(256) softmax_kernel(
    const int* __restrict__ mask, float* __restrict__ out) {
    __shared__ float red[8];
    int b = blockIdx.x, tid = threadIdx.x, wid = tid >> 5, lid = tid & 31;
    float v[8], mx = -3.0e38f;
    #pragma unroll
    for (int i = 0; i < 8; ++i) {
        int s = tid + i * 256;
        float x = out[b * S_DIM + s];
        if (mask[b * S_DIM + s] == 0) x = -1e9f;
        v[i] = x; mx = fmaxf(mx, x);
    }
    #pragma unroll
    for (int o = 16; o > 0; o >>= 1) mx = fmaxf(mx, __shfl_xor_sync(0xFFFFFFFFu, mx, o));
    if (lid == 0) red[wid] = mx;
    __syncthreads();
    mx = red[0];
    #pragma unroll
    for (int w = 1; w < 8; ++w) mx = fmaxf(mx, red[w]);
    float sum = 0.f;
    #pragma unroll
    for (int i = 0; i < 8; ++i) { v[i] = expf(v[i] - mx); sum += v[i]; }
    #pragma unroll
    for (int o = 16; o > 0; o >>= 1) sum += __shfl_xor_sync(0xFFFFFFFFu, sum, o);
    __syncthreads();
    if (lid == 0) red[wid] = sum;
    __syncthreads();
    sum = 0.f;
    #pragma unroll
    for (int w = 0; w < 8; ++w) sum += red[w];
    float inv = 1.f / sum;
    #pragma unroll
    for (int i = 0; i < 8; ++i) out[b * S_DIM + tid + i * 256] = v[i] * inv;
}

extern "C" void kernel_launch(void* const* d_in, const int* in_sizes, int n_in,
                              void* d_out, int out_size) {
    const float* dec  = (const float*)d_in[0];
    const float* enc  = (const float*)d_in[1];
    const int*   mask = (const int*)d_in[2];
    const float* wa_w = (const float*)d_in[3];
    const float* wa_b = (const float*)d_in[4];
    const float* ua_w = (const float*)d_in[5];
    const float* ua_b = (const float*)d_in[6];
    const float* va_w = (const float*)d_in[7];
    float* out = (float*)d_out;

    cudaFuncSetAttribute(gemm_kernel, cudaFuncAttributeMaxDynamicSharedMemorySize, SMEM_TOTAL);

    ut_split_kernel<<<dim3(32, 32), dim3(32, 8)>>>(ua_w);
    dvec_kernel<<<B_DIM * 4, 256>>>(dec, wa_w, wa_b, ua_b);
    gemm_kernel<<<(B_DIM * S_DIM) / M_TILE, 256, SMEM_TOTAL>>>(enc, va_w, out);
    softmax_kernel<<<B_DIM, 256>>>(mask, out);
}

// round 16
// speedup vs baseline: 1.0097x; 1.0097x over previous
#include <cuda_runtime.h>
#include <cuda_fp16.h>
#include <cstdint>

#define H_DIM 1024
#define S_DIM 2048
#define B_DIM 32
#define M_TILE 128
#define N_PASS 256
#define KC 64
#define NUM_G 64            // 4 passes x 16 K-chunks, continuous pipeline
#define NT 512              // 16 warps = 4 per SMSP

// smem layout
#define SMEM_DVEC 0
#define SMEM_VA   4096
#define SMEM_SCORE 8192     // 128 floats
#define SMEM_STAGES 9216
#define STAGE_SZ  49152     // A fp16 16KB + B fp16 32KB
#define SMEM_B_OFF 16384
#define SMEM_TOTAL (SMEM_STAGES + 3 * STAGE_SZ)   // 156672

__device__ __align__(16) __half g_a[(size_t)B_DIM * S_DIM * H_DIM];   // enc fp16, 128MB
__device__ __align__(16) __half g_ut[(size_t)H_DIM * H_DIM];          // Ua^T fp16, 2MB
__device__ float g_dvec[B_DIM * H_DIM];

__device__ __forceinline__ uint32_t smem_u32(const void* p) {
    uint32_t a;
    asm("{ .reg .u64 t; cvta.to.shared.u64 t, %1; cvt.u32.u64 %0, t; }" : "=r"(a) : "l"(p));
    return a;
}
__device__ __forceinline__ void cp16(uint32_t s, const void* g) {
    asm volatile("cp.async.cg.shared.global [%0], [%1], 16;" :: "r"(s), "l"(g));
}
#define CP_COMMIT() asm volatile("cp.async.commit_group;" ::: "memory")
#define CP_WAIT1()  asm volatile("cp.async.wait_group 1;" ::: "memory")

__device__ __forceinline__ void ldm4(uint32_t& r0, uint32_t& r1, uint32_t& r2, uint32_t& r3,
                                     uint32_t a) {
    asm volatile("ldmatrix.sync.aligned.m8n8.x4.shared.b16 {%0,%1,%2,%3}, [%4];"
                 : "=r"(r0), "=r"(r1), "=r"(r2), "=r"(r3) : "r"(a));
}
__device__ __forceinline__ void mma16816(float* c, const uint32_t* a, uint32_t b0, uint32_t b1) {
    asm volatile("mma.sync.aligned.m16n8k16.row.col.f32.f16.f16.f32 "
                 "{%0,%1,%2,%3}, {%4,%5,%6,%7}, {%8,%9}, {%0,%1,%2,%3};"
                 : "+f"(c[0]), "+f"(c[1]), "+f"(c[2]), "+f"(c[3])
                 : "r"(a[0]), "r"(a[1]), "r"(a[2]), "r"(a[3]), "r"(b0), "r"(b1));
}

// FMA/ALU-only tanh (no MUFU): exp2 range reduction + deg-5 poly + Newton rcp. abs err ~3e-5.
__device__ __forceinline__ float fast_tanh(float x) {
    x = fminf(9.0f, fmaxf(-9.0f, x));
    const float C = 2.885390082f;
    float zm = fmaf(x, C, 12582912.0f);
    int nb = __float_as_int(zm);
    float nf = zm - 12582912.0f;
    float f = fmaf(x, C, -nf);
    float p = 1.3333558e-3f;
    p = fmaf(p, f, 9.6181291e-3f);
    p = fmaf(p, f, 5.5504109e-2f);
    p = fmaf(p, f, 2.4022651e-1f);
    p = fmaf(p, f, 6.9314718e-1f);
    p = fmaf(p, f, 1.0f);
    float E = p * __int_as_float((nb + (127 - 0x4B400000)) << 23);
    float D = E + 1.0f;
    float r = __int_as_float((int)(0x7EF127EAu - (uint32_t)__float_as_int(D)));
    r = r * fmaf(-D, r, 2.0f);
    r = r * fmaf(-D, r, 2.0f);
    r = r * fmaf(-D, r, 2.0f);
    return fmaf(-2.0f, r, 1.0f);
}

// ---------------- enc fp32 -> fp16 ----------------
__global__ void __launch_bounds__(256) enc_split_kernel(const float* __restrict__ enc) {
    size_t i = (size_t)blockIdx.x * 256 + threadIdx.x;   // 16,777,216 float4s
    float4 v = ((const float4*)enc)[i];
    __half2 h0 = __floats2half2_rn(v.x, v.y);
    __half2 h1 = __floats2half2_rn(v.z, v.w);
    ((uint2*)g_a)[i] = make_uint2(*(uint32_t*)&h0, *(uint32_t*)&h1);
}

// ---------------- Ut[k][h] = Ua[h][k] as fp16 ----------------
__global__ void ut_split_kernel(const float* __restrict__ ua_w) {
    __shared__ float tile[32][33];
    int tx = threadIdx.x, ty = threadIdx.y;
    int k = blockIdx.x * 32 + tx, h0 = blockIdx.y * 32;
    #pragma unroll
    for (int i = 0; i < 32; i += 8)
        tile[ty + i][tx] = ua_w[(size_t)(h0 + ty + i) * H_DIM + k];
    __syncthreads();
    #pragma unroll
    for (int i = 0; i < 32; i += 8) {
        int kk = blockIdx.x * 32 + ty + i;
        g_ut[(size_t)kk * H_DIM + h0 + tx] = __float2half(tile[tx][ty + i]);
    }
}

// ---------------- dvec[b,k] = Wa_b[k]+Ua_b[k] + sum_h dec[b,h]*Wa[h,k] ----------------
__global__ void __launch_bounds__(256) dvec_kernel(
    const float* __restrict__ dec, const float* __restrict__ wa_w,
    const float* __restrict__ wa_b, const float* __restrict__ ua_b) {
    __shared__ float ds[H_DIM];
    int b = blockIdx.x >> 2, kc = blockIdx.x & 3, tid = threadIdx.x;
    #pragma unroll
    for (int i = 0; i < 4; ++i) ds[tid + i * 256] = dec[b * H_DIM + tid + i * 256];
    __syncthreads();
    int k = kc * 256 + tid;
    float acc = wa_b[k] + ua_b[k];
    #pragma unroll 8
    for (int h = 0; h < H_DIM; ++h) acc += ds[h] * __ldg(&wa_w[(size_t)h * H_DIM + k]);
    g_dvec[b * H_DIM + k] = acc;
}

// ---------------- fused GEMM (512 thr) + tanh + Va-dot -> raw scores ----------------
// M128 x N256 tile, all fills cp.async from pre-converted fp16; 16 warps, warp tile M32xN64.
__global__ void __launch_bounds__(NT, 1) gemm_kernel(
    const float* __restrict__ va_w, float* __restrict__ scores) {
    extern __shared__ __align__(128) char smem[];
    uint32_t sb = smem_u32(smem);
    int tid = threadIdx.x, lane = tid & 31, wid = tid >> 5;
    int warp_m = wid >> 2, warp_n = wid & 3;     // 4 x 4 warps: M32, N64 each
    int m0 = blockIdx.x * M_TILE;
    int bidx = m0 >> 11;

    if (tid < 256) {
        ((float4*)(smem + SMEM_DVEC))[tid] = ((const float4*)(g_dvec + bidx * H_DIM))[tid];
        ((float4*)(smem + SMEM_VA))[tid] = ((const float4*)va_w)[tid];
    }
    float* s_score = (float*)(smem + SMEM_SCORE);
    if (tid < M_TILE) s_score[tid] = 0.f;
    __syncthreads();
    const float* smd = (const float*)(smem + SMEM_DVEC);
    const float* smv = (const float*)(smem + SMEM_VA);

    // hoisted ldmatrix addressing
    int r8 = lane & 7, sel = lane >> 3;
    int selb = (sel & 1) << 3, selc = sel >> 1;
    uint32_t aOff = (uint32_t)((warp_m * 32 + selb + r8) * 128);
    uint32_t bOff = (uint32_t)((warp_n * 64 + selb + r8) * 128);
    uint32_t csw[4];
    #pragma unroll
    for (int ks = 0; ks < 4; ++ks) csw[ks] = (uint32_t)(((ks * 2 + selc) ^ r8) << 4);

    // hoisted fill addressing: A 1024 slots (2/thread), B 2048 slots (4/thread)
    int arow[2], aswf[2], ach[2];
    #pragma unroll
    for (int i = 0; i < 2; ++i) {
        int idx = tid + i * NT;
        arow[i] = idx >> 3; ach[i] = idx & 7;
        aswf[i] = arow[i] * 128 + ((ach[i] ^ (arow[i] & 7)) << 4);
    }
    int brow[4], bswf[4], bch[4];
    #pragma unroll
    for (int i = 0; i < 4; ++i) {
        int idx = tid + i * NT;
        brow[i] = idx >> 3; bch[i] = idx & 7;
        bswf[i] = SMEM_B_OFF + brow[i] * 128 + ((bch[i] ^ (brow[i] & 7)) << 4);
    }

    uint32_t stg[3];
    stg[0] = sb + SMEM_STAGES; stg[1] = stg[0] + STAGE_SZ; stg[2] = stg[1] + STAGE_SZ;

    float acc[2][8][4] = {};
    float partial[4] = {};

    // ---- prologue: stages 0,1 (chunks 0,1 of pass 0) ----
    #pragma unroll
    for (int g = 0; g < 2; ++g) {
        int k0 = g * KC;
        #pragma unroll
        for (int i = 0; i < 2; ++i)
            cp16(stg[g] + aswf[i], g_a + (size_t)(m0 + arow[i]) * H_DIM + k0 + ach[i] * 8);
        #pragma unroll
        for (int i = 0; i < 4; ++i)
            cp16(stg[g] + bswf[i], g_ut + (size_t)brow[i] * H_DIM + k0 + bch[i] * 8);
        CP_COMMIT();
    }

    // ---- main: 64 chunks, one barrier per chunk, 3-stage pipeline ----
    for (int g = 0; g < NUM_G; ++g) {
        CP_WAIT1();
        __syncthreads();

        int gf = g + 2;
        if (gf < NUM_G) {
            int k0f = (gf & 15) * KC;
            int n0f = (gf >> 4) * N_PASS;
            uint32_t stf = stg[gf % 3];
            #pragma unroll
            for (int i = 0; i < 2; ++i)
                cp16(stf + aswf[i], g_a + (size_t)(m0 + arow[i]) * H_DIM + k0f + ach[i] * 8);
            #pragma unroll
            for (int i = 0; i < 4; ++i)
                cp16(stf + bswf[i], g_ut + (size_t)(n0f + brow[i]) * H_DIM + k0f + bch[i] * 8);
        }
        CP_COMMIT();

        uint32_t sA = stg[g % 3] + aOff, sB = stg[g % 3] + SMEM_B_OFF + bOff;
        #pragma unroll
        for (int ks = 0; ks < 4; ++ks) {
            uint32_t aAdr = sA + csw[ks], bAdr = sB + csw[ks];
            uint32_t a[2][4], b[4][4];
            #pragma unroll
            for (int mf = 0; mf < 2; ++mf)
                ldm4(a[mf][0], a[mf][1], a[mf][2], a[mf][3], aAdr + mf * 2048);
            #pragma unroll
            for (int nf2 = 0; nf2 < 4; ++nf2)
                ldm4(b[nf2][0], b[nf2][1], b[nf2][2], b[nf2][3], bAdr + nf2 * 2048);
            #pragma unroll
            for (int mf = 0; mf < 2; ++mf)
                #pragma unroll
                for (int nf = 0; nf < 8; ++nf)
                    mma16816(acc[mf][nf], a[mf], b[nf >> 1][nf & 1], b[nf >> 1][(nf & 1) + 2]);
        }

        // per-pass epilogue: tanh(acc + dvec) . Va, reset accumulators
        if ((g & 15) == 15) {
            int n0 = (g >> 4) * N_PASS;
            #pragma unroll
            for (int nf = 0; nf < 8; ++nf) {
                int col = n0 + warp_n * 64 + nf * 8 + (lane & 3) * 2;
                float dx = smd[col], dy = smd[col + 1];
                float vx = smv[col], vy = smv[col + 1];
                #pragma unroll
                for (int mf = 0; mf < 2; ++mf) {
                    float* c = acc[mf][nf];
                    partial[mf * 2 + 0] += vx * fast_tanh(c[0] + dx) + vy * fast_tanh(c[1] + dy);
                    partial[mf * 2 + 1] += vx * fast_tanh(c[2] + dx) + vy * fast_tanh(c[3] + dy);
                    c[0] = c[1] = c[2] = c[3] = 0.f;
                }
            }
        }
    }

    // reduce per-thread partials -> per-row scores
    #pragma unroll
    for (int p = 0; p < 4; ++p) {
        float v = partial[p];
        v += __shfl_xor_sync(0xFFFFFFFFu, v, 1);
        v += __shfl_xor_sync(0xFFFFFFFFu, v, 2);
        if ((lane & 3) == 0) {
            int row = warp_m * 32 + (p >> 1) * 16 + (p & 1) * 8 + (lane >> 2);
            atomicAdd(&s_score[row], v);
        }
    }
    __syncthreads();
    if (tid < M_TILE) scores[m0 + tid] = s_score[tid];
}

// ---------------- masked softmax over S, in place ----------------
__global__ void __launch_bounds__(256) softmax_kernel(
    const int* __restrict__ mask, float* __restrict__ out) {
    __shared__ float red[8];
    int b = blockIdx.x, tid = threadIdx.x, wid = tid >> 5, lid = tid & 31;
    float v[8], mx = -3.0e38f;
    #pragma unroll
    for (int i = 0; i < 8; ++i) {
        int s = tid + i * 256;
        float x = out[b * S_DIM + s];
        if (mask[b * S_DIM + s] == 0) x = -1e9f;
        v[i] = x; mx = fmaxf(mx, x);
    }
    #pragma unroll
    for (int o = 16; o > 0; o >>= 1) mx = fmaxf(mx, __shfl_xor_sync(0xFFFFFFFFu, mx, o));
    if (lid == 0) red[wid] = mx;
    __syncthreads();
    mx = red[0];
    #pragma unroll
    for (int w = 1; w < 8; ++w) mx = fmaxf(mx, red[w]);
    float sum = 0.f;
    #pragma unroll
    for (int i = 0; i < 8; ++i) { v[i] = expf(v[i] - mx); sum += v[i]; }
    #pragma unroll
    for (int o = 16; o > 0; o >>= 1) sum += __shfl_xor_sync(0xFFFFFFFFu, sum, o);
    __syncthreads();
    if (lid == 0) red[wid] = sum;
    __syncthreads();
    sum = 0.f;
    #pragma unroll
    for (int w = 0; w < 8; ++w) sum += red[w];
    float inv = 1.f / sum;
    #pragma unroll
    for (int i = 0; i < 8; ++i) out[b * S_DIM + tid + i * 256] = v[i] * inv;
}

extern "C" void kernel_launch(void* const* d_in, const int* in_sizes, int n_in,
                              void* d_out, int out_size) {
    const float* dec  = (const float*)d_in[0];
    const float* enc  = (const float*)d_in[1];
    const int*   mask = (const int*)d_in[2];
    const float* wa_w = (const float*)d_in[3];
    const float* wa_b = (const float*)d_in[4];
    const float* ua_w = (const float*)d_in[5];
    const float* ua_b = (const float*)d_in[6];
    const float* va_w = (const float*)d_in[7];
    float* out = (float*)d_out;

    cudaFuncSetAttribute(gemm_kernel, cudaFuncAttributeMaxDynamicSharedMemorySize, SMEM_TOTAL);

    enc_split_kernel<<<(B_DIM * S_DIM * H_DIM) / (4 * 256), 256>>>(enc);
    ut_split_kernel<<<dim3(32, 32), dim3(32, 8)>>>(ua_w);
    dvec_kernel<<<B_DIM * 4, 256>>>(dec, wa_w, wa_b, ua_b);
    gemm_kernel<<<(B_DIM * S_DIM) / M_TILE, NT, SMEM_TOTAL>>>(va_w, out);
    softmax_kernel<<<B_DIM, 256>>>(mask, out);
}